// round 3
// baseline (speedup 1.0000x reference)
#include <cuda_runtime.h>
#include <math.h>
#include <stdint.h>

#define NH 8
#define CDIM 512
#define HW 256
#define CH 64
#define BATCH 4
#define TT 64
#define TCACHE 63
#define STR 68

__device__ float g_wqkv_n[3 * CDIM * CDIM];
__device__ float g_wproj_n[CDIM * CDIM];
__device__ float g_rope_cos[TT * 32];
__device__ float g_rope_sin[TT * 32];
__device__ float g_q[BATCH * NH * HW * CH];
__device__ float g_k[BATCH * NH * HW * CH];
__device__ float g_v[BATCH * NH * HW * CH];
__device__ float g_o[BATCH * CDIM * HW];   // [b][ch*NH+head][s]

__device__ __forceinline__ unsigned f2tf(float x) {
    unsigned r;
    asm("cvt.rna.tf32.f32 %0, %1;" : "=r"(r) : "f"(x));
    return r;
}

__device__ __forceinline__ void mma8(float c[4], const unsigned a[4], unsigned b0, unsigned b1) {
    asm volatile(
        "mma.sync.aligned.m16n8k8.row.col.f32.tf32.tf32.f32 "
        "{%0,%1,%2,%3}, {%4,%5,%6,%7}, {%8,%9}, {%0,%1,%2,%3};\n"
        : "+f"(c[0]), "+f"(c[1]), "+f"(c[2]), "+f"(c[3])
        : "r"(a[0]), "r"(a[1]), "r"(a[2]), "r"(a[3]), "r"(b0), "r"(b1));
}

// permute within group-of-8 on reduction dim: logical r -> physical ((r&3)<<1)|(r>>2)
// so mma frag pairs (r, r+4) sit adjacent -> uint2 shared loads
__device__ __forceinline__ int pc8(int r) { return ((r & 3) << 1) | (r >> 2); }

// ---------------- K1a: mp_weight row normalization ----------------
__global__ void norm_kernel(const float* __restrict__ wq, const float* __restrict__ wp) {
    int r = blockIdx.x;
    const float* src;
    float* dst;
    if (r < 3 * CDIM) { src = wq + (size_t)r * CDIM; dst = g_wqkv_n + (size_t)r * CDIM; }
    else { int rr = r - 3 * CDIM; src = wp + (size_t)rr * CDIM; dst = g_wproj_n + (size_t)rr * CDIM; }

    float4 v = reinterpret_cast<const float4*>(src)[threadIdx.x];
    float ss = v.x * v.x + v.y * v.y + v.z * v.z + v.w * v.w;
    for (int o = 16; o; o >>= 1) ss += __shfl_xor_sync(0xffffffffu, ss, o);
    __shared__ float wsum[4];
    if ((threadIdx.x & 31) == 0) wsum[threadIdx.x >> 5] = ss;
    __syncthreads();
    float nrm = sqrtf(wsum[0] + wsum[1] + wsum[2] + wsum[3]);
    float s512 = sqrtf((float)CDIM);
    float scale = 1.0f / ((1e-4f + nrm / s512) * s512);
    float4 o4;
    o4.x = v.x * scale; o4.y = v.y * scale; o4.z = v.z * scale; o4.w = v.w * scale;
    reinterpret_cast<float4*>(dst)[threadIdx.x] = o4;
}

// ---------------- K1b: rope table ----------------
__global__ void rope_table_kernel() {
    int idx = blockIdx.x * blockDim.x + threadIdx.x;
    if (idx < TT * 32) {
        int t = idx >> 5, j = idx & 31;
        float inv = powf(10000.0f, -(2.0f * (float)j) / 64.0f);
        float ang = (float)t * inv;
        g_rope_cos[idx] = cosf(ang);
        g_rope_sin[idx] = sinf(ang);
    }
}

// ---------------- K2: QKV GEMM (fp32) -> q/k/v [b][head][s][ch] ----------------
__global__ __launch_bounds__(256) void qkv_gemm_kernel(const float* __restrict__ x) {
    __shared__ float As[16][68];
    __shared__ float Bs[16][68];
    int bb = blockIdx.z;
    int m0 = blockIdx.y * 64;
    int n0 = blockIdx.x * 64;
    int tid = threadIdx.x;
    int ty = tid >> 4, tx = tid & 15;
    float acc[4][4] = {};

    for (int k0 = 0; k0 < CDIM; k0 += 16) {
        {
            int lin = tid * 4;
            int mi = lin >> 4, ki = lin & 15;
            float4 a = *reinterpret_cast<const float4*>(&g_wqkv_n[(size_t)(m0 + mi) * CDIM + k0 + ki]);
            As[ki + 0][mi] = a.x; As[ki + 1][mi] = a.y; As[ki + 2][mi] = a.z; As[ki + 3][mi] = a.w;
        }
        {
            int lin = tid * 4;
            int ki = lin >> 6, ni = lin & 63;
            float4 b = *reinterpret_cast<const float4*>(&x[((size_t)bb * CDIM + k0 + ki) * HW + n0 + ni]);
            *reinterpret_cast<float4*>(&Bs[ki][ni]) = b;
        }
        __syncthreads();
#pragma unroll
        for (int kk = 0; kk < 16; kk++) {
            float4 a = *reinterpret_cast<const float4*>(&As[kk][ty * 4]);
            float4 b = *reinterpret_cast<const float4*>(&Bs[kk][tx * 4]);
            float av[4] = {a.x, a.y, a.z, a.w};
            float bv[4] = {b.x, b.y, b.z, b.w};
#pragma unroll
            for (int i = 0; i < 4; i++)
#pragma unroll
                for (int j = 0; j < 4; j++) acc[i][j] += av[i] * bv[j];
        }
        __syncthreads();
    }

    int which = m0 >> 9;
    int head = (m0 >> 6) & 7;
    float* dst = (which == 0) ? g_q : ((which == 1) ? g_k : g_v);
#pragma unroll
    for (int i = 0; i < 4; i++) {
        int ch = ty * 4 + i;
#pragma unroll
        for (int j = 0; j < 4; j++) {
            int s = n0 + tx * 4 + j;
            dst[(((size_t)bb * NH + head) * HW + s) * CH + ch] = acc[i][j];
        }
    }
}

// ---------------- K3: flash attention (tf32 mma, rope fused) ----------------
__global__ __launch_bounds__(128) void attn_kernel(const float* __restrict__ ck,
                                                   const float* __restrict__ cv) {
    extern __shared__ unsigned sm[];
    unsigned* Ks = sm;                 // [key][ch perm]
    unsigned* Vs = sm + 64 * STR;      // [ch][key perm]
    unsigned* Ps = sm + 2 * 64 * STR;  // Q stage, then P [q][key perm]

    int qt = blockIdx.x, head = blockIdx.y, bb = blockIdx.z;
    int tid = threadIdx.x;
    int w = tid >> 5, l = tid & 31;
    int lrow = tid >> 1;
    int lc0 = (tid & 1) * 32;

    // stage Q: rope(pos 63) * 1/8, tf32, ch-permuted
    {
        const float* qp = g_q + (((size_t)bb * NH + head) * HW + qt * 64 + lrow) * CH;
        const float* cs = g_rope_cos + 63 * 32;
        const float* sn = g_rope_sin + 63 * 32;
#pragma unroll
        for (int i = 0; i < 8; i++) {
            int ch = lc0 + i * 4;
            float4 v = *reinterpret_cast<const float4*>(qp + ch);
            int j = ch >> 1;
            float c0 = cs[j], s0 = sn[j], c1 = cs[j + 1], s1 = sn[j + 1];
            float r0 = (v.x * c0 - v.y * s0) * 0.125f;
            float r1 = (v.x * s0 + v.y * c0) * 0.125f;
            float r2 = (v.z * c1 - v.w * s1) * 0.125f;
            float r3 = (v.z * s1 + v.w * c1) * 0.125f;
            int g = ch & ~7, rr = ch & 7;
            Ps[lrow * STR + g + pc8(rr)]     = f2tf(r0);
            Ps[lrow * STR + g + pc8(rr + 1)] = f2tf(r1);
            Ps[lrow * STR + g + pc8(rr + 2)] = f2tf(r2);
            Ps[lrow * STR + g + pc8(rr + 3)] = f2tf(r3);
        }
    }
    __syncthreads();

    unsigned qa[8][4];
    int r0 = 16 * w + (l >> 2);
    int coff = 2 * (l & 3);
#pragma unroll
    for (int kk = 0; kk < 8; kk++) {
        int col = kk * 8 + coff;
        uint2 p0 = *reinterpret_cast<const uint2*>(&Ps[r0 * STR + col]);
        uint2 p1 = *reinterpret_cast<const uint2*>(&Ps[(r0 + 8) * STR + col]);
        qa[kk][0] = p0.x; qa[kk][1] = p1.x; qa[kk][2] = p0.y; qa[kk][3] = p1.y;
    }

    float oacc[8][4] = {};
    float rm0 = -1e30f, rm1 = -1e30f, lsum0 = 0.f, lsum1 = 0.f;

    for (int kt = 0; kt < 256; kt++) {
        int t = kt >> 2, st = kt & 3;
        const float *kp, *vp;
        if (t < TCACHE) {
            size_t base = ((((size_t)bb * NH + head) * TCACHE + t) * HW + st * 64);
            kp = ck + base * CH;
            vp = cv + base * CH;
        } else {
            size_t base = (((size_t)bb * NH + head) * HW + st * 64);
            kp = g_k + base * CH;
            vp = g_v + base * CH;
        }
        __syncthreads();

        {
            const float* cs = g_rope_cos + t * 32;
            const float* sn = g_rope_sin + t * 32;
#pragma unroll
            for (int i = 0; i < 8; i++) {
                int ch = lc0 + i * 4;
                float4 v = *reinterpret_cast<const float4*>(kp + (size_t)lrow * CH + ch);
                int j = ch >> 1;
                float c0 = cs[j], s0 = sn[j], c1 = cs[j + 1], s1 = sn[j + 1];
                float a0 = v.x * c0 - v.y * s0;
                float a1 = v.x * s0 + v.y * c0;
                float a2 = v.z * c1 - v.w * s1;
                float a3 = v.z * s1 + v.w * c1;
                int g = ch & ~7, rr = ch & 7;
                Ks[lrow * STR + g + pc8(rr)]     = f2tf(a0);
                Ks[lrow * STR + g + pc8(rr + 1)] = f2tf(a1);
                Ks[lrow * STR + g + pc8(rr + 2)] = f2tf(a2);
                Ks[lrow * STR + g + pc8(rr + 3)] = f2tf(a3);
            }
            int key = lrow;
            int pk = (key & ~7) | pc8(key & 7);
#pragma unroll
            for (int i = 0; i < 8; i++) {
                int ch = lc0 + i * 4;
                float4 v = *reinterpret_cast<const float4*>(vp + (size_t)key * CH + ch);
                Vs[(ch + 0) * STR + pk] = f2tf(v.x);
                Vs[(ch + 1) * STR + pk] = f2tf(v.y);
                Vs[(ch + 2) * STR + pk] = f2tf(v.z);
                Vs[(ch + 3) * STR + pk] = f2tf(v.w);
            }
        }
        __syncthreads();

        // S = Q K^T
        float sc[8][4];
#pragma unroll
        for (int nn = 0; nn < 8; nn++) {
            sc[nn][0] = sc[nn][1] = sc[nn][2] = sc[nn][3] = 0.f;
            int krow = (nn * 8 + (l >> 2)) * STR;
#pragma unroll
            for (int kk = 0; kk < 8; kk++) {
                uint2 b = *reinterpret_cast<const uint2*>(&Ks[krow + kk * 8 + coff]);
                mma8(sc[nn], qa[kk], b.x, b.y);
            }
        }

        // online softmax
        float mx0 = -1e30f, mx1 = -1e30f;
#pragma unroll
        for (int nn = 0; nn < 8; nn++) {
            mx0 = fmaxf(mx0, fmaxf(sc[nn][0], sc[nn][1]));
            mx1 = fmaxf(mx1, fmaxf(sc[nn][2], sc[nn][3]));
        }
        mx0 = fmaxf(mx0, __shfl_xor_sync(0xffffffffu, mx0, 1));
        mx0 = fmaxf(mx0, __shfl_xor_sync(0xffffffffu, mx0, 2));
        mx1 = fmaxf(mx1, __shfl_xor_sync(0xffffffffu, mx1, 1));
        mx1 = fmaxf(mx1, __shfl_xor_sync(0xffffffffu, mx1, 2));
        float mn0 = fmaxf(rm0, mx0), mn1 = fmaxf(rm1, mx1);
        float al0 = __expf(rm0 - mn0), al1 = __expf(rm1 - mn1);
        float s0 = 0.f, s1 = 0.f;
#pragma unroll
        for (int nn = 0; nn < 8; nn++) {
            float p0 = __expf(sc[nn][0] - mn0);
            float p1 = __expf(sc[nn][1] - mn0);
            float p2 = __expf(sc[nn][2] - mn1);
            float p3 = __expf(sc[nn][3] - mn1);
            s0 += p0 + p1; s1 += p2 + p3;
            int kb = nn * 8;
            Ps[r0 * STR + kb + pc8(coff)]           = f2tf(p0);
            Ps[r0 * STR + kb + pc8(coff + 1)]       = f2tf(p1);
            Ps[(r0 + 8) * STR + kb + pc8(coff)]     = f2tf(p2);
            Ps[(r0 + 8) * STR + kb + pc8(coff + 1)] = f2tf(p3);
        }
        s0 += __shfl_xor_sync(0xffffffffu, s0, 1);
        s0 += __shfl_xor_sync(0xffffffffu, s0, 2);
        s1 += __shfl_xor_sync(0xffffffffu, s1, 1);
        s1 += __shfl_xor_sync(0xffffffffu, s1, 2);
        lsum0 = lsum0 * al0 + s0;
        lsum1 = lsum1 * al1 + s1;
        rm0 = mn0; rm1 = mn1;
#pragma unroll
        for (int nn = 0; nn < 8; nn++) {
            oacc[nn][0] *= al0; oacc[nn][1] *= al0;
            oacc[nn][2] *= al1; oacc[nn][3] *= al1;
        }
        __syncwarp();  // P rows are warp-private

        // O += P V
#pragma unroll
        for (int kk = 0; kk < 8; kk++) {
            int col = kk * 8 + coff;
            uint2 pA = *reinterpret_cast<const uint2*>(&Ps[r0 * STR + col]);
            uint2 pB = *reinterpret_cast<const uint2*>(&Ps[(r0 + 8) * STR + col]);
            unsigned a[4] = {pA.x, pB.x, pA.y, pB.y};
#pragma unroll
            for (int nn = 0; nn < 8; nn++) {
                uint2 b = *reinterpret_cast<const uint2*>(&Vs[(nn * 8 + (l >> 2)) * STR + col]);
                mma8(oacc[nn], a, b.x, b.y);
            }
        }
    }

    float inv0 = 1.0f / lsum0, inv1 = 1.0f / lsum1;
    int q0 = qt * 64 + 16 * w + (l >> 2);
#pragma unroll
    for (int nn = 0; nn < 8; nn++) {
        int ch = nn * 8 + coff;
        size_t i00 = ((size_t)bb * CDIM + (ch * NH + head)) * HW;
        size_t i01 = ((size_t)bb * CDIM + ((ch + 1) * NH + head)) * HW;
        g_o[i00 + q0]     = oacc[nn][0] * inv0;
        g_o[i01 + q0]     = oacc[nn][1] * inv0;
        g_o[i00 + q0 + 8] = oacc[nn][2] * inv1;
        g_o[i01 + q0 + 8] = oacc[nn][3] * inv1;
    }
}

// ---------------- K4: proj GEMM + mp_sum ----------------
__global__ __launch_bounds__(256) void proj_kernel(const float* __restrict__ x,
                                                   float* __restrict__ out) {
    __shared__ float As[16][68];
    __shared__ float Bs[16][68];
    int bb = blockIdx.z;
    int m0 = blockIdx.y * 64;
    int n0 = blockIdx.x * 64;
    int tid = threadIdx.x;
    int ty = tid >> 4, tx = tid & 15;
    float acc[4][4] = {};

    for (int k0 = 0; k0 < CDIM; k0 += 16) {
        {
            int lin = tid * 4;
            int mi = lin >> 4, ki = lin & 15;
            float4 a = *reinterpret_cast<const float4*>(&g_wproj_n[(size_t)(m0 + mi) * CDIM + k0 + ki]);
            As[ki + 0][mi] = a.x; As[ki + 1][mi] = a.y; As[ki + 2][mi] = a.z; As[ki + 3][mi] = a.w;
        }
        {
            int lin = tid * 4;
            int ki = lin >> 6, ni = lin & 63;
            float4 b = *reinterpret_cast<const float4*>(&g_o[((size_t)bb * CDIM + k0 + ki) * HW + n0 + ni]);
            *reinterpret_cast<float4*>(&Bs[ki][ni]) = b;
        }
        __syncthreads();
#pragma unroll
        for (int kk = 0; kk < 16; kk++) {
            float4 a = *reinterpret_cast<const float4*>(&As[kk][ty * 4]);
            float4 b = *reinterpret_cast<const float4*>(&Bs[kk][tx * 4]);
            float av[4] = {a.x, a.y, a.z, a.w};
            float bv[4] = {b.x, b.y, b.z, b.w};
#pragma unroll
            for (int i = 0; i < 4; i++)
#pragma unroll
                for (int j = 0; j < 4; j++) acc[i][j] += av[i] * bv[j];
        }
        __syncthreads();
    }

    const float norm = 1.3130643286f;  // 1/sqrt(0.58)
#pragma unroll
    for (int i = 0; i < 4; i++) {
        int och = m0 + ty * 4 + i;
#pragma unroll
        for (int j = 0; j < 4; j++) {
            int s = n0 + tx * 4 + j;
            size_t idx = ((size_t)bb * CDIM + och) * HW + s;
            out[idx] = (0.7f * x[idx] + 0.3f * acc[i][j]) * norm;
        }
    }
}

extern "C" void kernel_launch(void* const* d_in, const int* in_sizes, int n_in,
                              void* d_out, int out_size) {
    const float* x     = (const float*)d_in[0];
    const float* ck    = (const float*)d_in[1];
    const float* cv    = (const float*)d_in[2];
    const float* wqkv  = (const float*)d_in[3];
    const float* wproj = (const float*)d_in[4];
    float* out = (float*)d_out;

    norm_kernel<<<4 * CDIM, 128>>>(wqkv, wproj);
    rope_table_kernel<<<8, 256>>>();
    qkv_gemm_kernel<<<dim3(4, 24, 4), 256>>>(x);

    int smem = 3 * 64 * STR * sizeof(unsigned);
    cudaFuncSetAttribute(attn_kernel, cudaFuncAttributeMaxDynamicSharedMemorySize, smem);
    attn_kernel<<<dim3(4, NH, 4), 128, smem>>>(ck, cv);

    proj_kernel<<<dim3(4, 8, 4), 256>>>(x, out);
}

// round 5
// speedup vs baseline: 1.7883x; 1.7883x over previous
#include <cuda_runtime.h>
#include <math.h>
#include <stdint.h>

#define NH 8
#define CDIM 512
#define HW 256
#define CH 64
#define BATCH 4
#define TCACHE 63
#define SK 72                 // smem row stride (words) for K/V/Vt/P buffers
#define LOG2E 1.4426950408889634f

__device__ float g_wqkv_n[3 * CDIM * CDIM];
__device__ float g_wproj_n[CDIM * CDIM];
__device__ float2 g_rope[64 * 32];          // {cos,sin}[t][j]
__device__ float g_q[BATCH * NH * HW * CH];
__device__ float g_k[BATCH * NH * HW * CH];
__device__ float g_v[BATCH * NH * HW * CH];
__device__ float g_o[BATCH * CDIM * HW];    // [b][ch*NH+head][s]
// split-KV partials: [(((b*8+h)*2+qp)*2+kvh)] x [ch 64][row 128]
__device__ float g_po[BATCH * NH * 2 * 2 * 64 * 128];
__device__ float g_pm[BATCH * NH * 2 * 2 * 128];
__device__ float g_pl[BATCH * NH * 2 * 2 * 128];

__device__ __forceinline__ unsigned f2tf(float x) {
    unsigned r;
    asm("cvt.rna.tf32.f32 %0, %1;" : "=r"(r) : "f"(x));
    return r;
}
__device__ __forceinline__ float ex2(float x) {
    float y;
    asm("ex2.approx.f32 %0, %1;" : "=f"(y) : "f"(x));
    return y;
}
__device__ __forceinline__ void mma8(float c[4], const unsigned a[4], unsigned b0, unsigned b1) {
    asm volatile(
        "mma.sync.aligned.m16n8k8.row.col.f32.tf32.tf32.f32 "
        "{%0,%1,%2,%3}, {%4,%5,%6,%7}, {%8,%9}, {%0,%1,%2,%3};\n"
        : "+f"(c[0]), "+f"(c[1]), "+f"(c[2]), "+f"(c[3])
        : "r"(a[0]), "r"(a[1]), "r"(a[2]), "r"(a[3]), "r"(b0), "r"(b1));
}
// logical index r (0..7) within an 8-group -> physical slot, so that the
// tf32 B/A fragment pair (r, r+4) sits at adjacent physical slots (2r, 2r+1)
__device__ __forceinline__ int pc8(int r) { return ((r & 3) << 1) | (r >> 2); }

__device__ __forceinline__ void cpa16(uint32_t dst, const void* src) {
    asm volatile("cp.async.cg.shared.global [%0], [%1], 16;" :: "r"(dst), "l"(src));
}
#define CP_COMMIT() asm volatile("cp.async.commit_group;")
#define CP_WAIT1()  asm volatile("cp.async.wait_group 1;")

// ---------------- K1a: mp_weight row normalization ----------------
__global__ void norm_kernel(const float* __restrict__ wq, const float* __restrict__ wp) {
    int r = blockIdx.x;
    const float* src;
    float* dst;
    if (r < 3 * CDIM) { src = wq + (size_t)r * CDIM; dst = g_wqkv_n + (size_t)r * CDIM; }
    else { int rr = r - 3 * CDIM; src = wp + (size_t)rr * CDIM; dst = g_wproj_n + (size_t)rr * CDIM; }

    float4 v = reinterpret_cast<const float4*>(src)[threadIdx.x];
    float ss = v.x * v.x + v.y * v.y + v.z * v.z + v.w * v.w;
    for (int o = 16; o; o >>= 1) ss += __shfl_xor_sync(0xffffffffu, ss, o);
    __shared__ float wsum[4];
    if ((threadIdx.x & 31) == 0) wsum[threadIdx.x >> 5] = ss;
    __syncthreads();
    float nrm = sqrtf(wsum[0] + wsum[1] + wsum[2] + wsum[3]);
    float s512 = sqrtf((float)CDIM);
    float scale = 1.0f / ((1e-4f + nrm / s512) * s512);
    float4 o4;
    o4.x = v.x * scale; o4.y = v.y * scale; o4.z = v.z * scale; o4.w = v.w * scale;
    reinterpret_cast<float4*>(dst)[threadIdx.x] = o4;
}

// ---------------- K1b: rope table ----------------
__global__ void rope_table_kernel() {
    int idx = blockIdx.x * blockDim.x + threadIdx.x;
    if (idx < 64 * 32) {
        int t = idx >> 5, j = idx & 31;
        float inv = powf(10000.0f, -(2.0f * (float)j) / 64.0f);
        float a = (float)t * inv;
        g_rope[idx] = make_float2(cosf(a), sinf(a));
    }
}

// ---------------- K2: QKV GEMM (fp32) -> q/k/v [b][head][s][ch] ----------------
__global__ __launch_bounds__(256) void qkv_gemm_kernel(const float* __restrict__ x) {
    __shared__ float As[16][68];
    __shared__ float Bs[16][68];
    int bb = blockIdx.z;
    int m0 = blockIdx.y * 64;
    int n0 = blockIdx.x * 64;
    int tid = threadIdx.x;
    int ty = tid >> 4, tx = tid & 15;
    float acc[4][4] = {};

    for (int k0 = 0; k0 < CDIM; k0 += 16) {
        {
            int lin = tid * 4;
            int mi = lin >> 4, ki = lin & 15;
            float4 a = *reinterpret_cast<const float4*>(&g_wqkv_n[(size_t)(m0 + mi) * CDIM + k0 + ki]);
            As[ki + 0][mi] = a.x; As[ki + 1][mi] = a.y; As[ki + 2][mi] = a.z; As[ki + 3][mi] = a.w;
        }
        {
            int lin = tid * 4;
            int ki = lin >> 6, ni = lin & 63;
            float4 b = *reinterpret_cast<const float4*>(&x[((size_t)bb * CDIM + k0 + ki) * HW + n0 + ni]);
            *reinterpret_cast<float4*>(&Bs[ki][ni]) = b;
        }
        __syncthreads();
#pragma unroll
        for (int kk = 0; kk < 16; kk++) {
            float4 a = *reinterpret_cast<const float4*>(&As[kk][ty * 4]);
            float4 b = *reinterpret_cast<const float4*>(&Bs[kk][tx * 4]);
            float av[4] = {a.x, a.y, a.z, a.w};
            float bv[4] = {b.x, b.y, b.z, b.w};
#pragma unroll
            for (int i = 0; i < 4; i++)
#pragma unroll
                for (int j = 0; j < 4; j++) acc[i][j] += av[i] * bv[j];
        }
        __syncthreads();
    }

    int which = m0 >> 9;
    int head = (m0 >> 6) & 7;
    float* dst = (which == 0) ? g_q : ((which == 1) ? g_k : g_v);
#pragma unroll
    for (int i = 0; i < 4; i++) {
        int ch = ty * 4 + i;
#pragma unroll
        for (int j = 0; j < 4; j++) {
            int s = n0 + tx * 4 + j;
            dst[(((size_t)bb * NH + head) * HW + s) * CH + ch] = acc[i][j];
        }
    }
}

// ---------------- K3: flash attention v2 ----------------
// grid (4, 8, 4): x -> qp = x>>1 (128-q-row block), kvh = x&1 (128-kv-subtile half)
// block 128 threads. 2 q-tiles of 64 per CTA; cp.async double-buffered K/V;
// shared K rope+permute and V transpose+permute conversion passes.
__global__ __launch_bounds__(128, 1) void attn_kernel(const float* __restrict__ ck,
                                                      const float* __restrict__ cv) {
    extern __shared__ float smf[];
    float* Kr = smf;                  // 2 stages x 64 x SK  (raw -> roped+permuted in place)
    float* Vr = smf + 2 * 64 * SK;    // 2 stages x 64 x SK  (raw)
    float* Vt = smf + 4 * 64 * SK;    // 64 ch x SK          (transposed, key-permuted)
    float* Ps = smf + 5 * 64 * SK;    // 128 q x SK          (Q staging, then P)
    float2* Tab = reinterpret_cast<float2*>(smf + 7 * 64 * SK);  // 64 x 32

    int qp = blockIdx.x >> 1, kvh = blockIdx.x & 1;
    int head = blockIdx.y, bb = blockIdx.z;
    int bhi = bb * NH + head;
    int tid = threadIdx.x;
    int w = tid >> 5, l = tid & 31;
    int la = l >> 2, lb = l & 3;

    uint32_t kr_u = (uint32_t)__cvta_generic_to_shared(Kr);
    uint32_t vr_u = (uint32_t)__cvta_generic_to_shared(Vr);

    // -------- issue helper (cp.async K+V tile for iteration i into stage i&1) ----
    auto issue_tile = [&](int i) {
        int ktg = kvh * 128 + i;
        int t = ktg >> 2, st = ktg & 3;
        const float *kp, *vp;
        if (t < TCACHE) {
            size_t base = (((size_t)bhi * TCACHE + t) * HW + st * 64);
            kp = ck + base * CH; vp = cv + base * CH;
        } else {
            size_t base = ((size_t)bhi * HW + st * 64);
            kp = g_k + base * CH; vp = g_v + base * CH;
        }
        int s = i & 1;
        int krow = tid >> 1, half = tid & 1;
        uint32_t kd = kr_u + (uint32_t)(s * 64 * SK + krow * SK + half * 32) * 4u;
        uint32_t vd = vr_u + (uint32_t)(s * 64 * SK + krow * SK + half * 32) * 4u;
        const float* ks = kp + krow * CH + half * 32;
        const float* vs = vp + krow * CH + half * 32;
#pragma unroll
        for (int c = 0; c < 8; c++) {
            cpa16(kd + c * 16, ks + c * 4);
            cpa16(vd + c * 16, vs + c * 4);
        }
    };

    issue_tile(0); CP_COMMIT();
    issue_tile(1); CP_COMMIT();

    // -------- rope table -> smem --------
#pragma unroll
    for (int i = 0; i < 16; i++) Tab[tid + i * 128] = g_rope[tid + i * 128];
    __syncthreads();

    // -------- stage Q: rope(pos 63), scale by log2e/8, tf32, permuted --------
    {
        int r = tid;  // 0..127
        const float* qpv = g_q + (((size_t)bhi) * HW + qp * 128 + r) * CH;
        const float2* tq = Tab + 63 * 32;
        const float sc = 0.125f * LOG2E;
        unsigned* pr = reinterpret_cast<unsigned*>(Ps + r * SK);
#pragma unroll
        for (int g = 0; g < 8; g++) {
            float4 x0 = *reinterpret_cast<const float4*>(qpv + 8 * g);
            float4 x1 = *reinterpret_cast<const float4*>(qpv + 8 * g + 4);
            float2 t0 = tq[4 * g], t1 = tq[4 * g + 1], t2 = tq[4 * g + 2], t3 = tq[4 * g + 3];
            float l0 = (x0.x * t0.x - x0.y * t0.y) * sc;
            float l1 = (x0.x * t0.y + x0.y * t0.x) * sc;
            float l2 = (x0.z * t1.x - x0.w * t1.y) * sc;
            float l3 = (x0.z * t1.y + x0.w * t1.x) * sc;
            float l4 = (x1.x * t2.x - x1.y * t2.y) * sc;
            float l5 = (x1.x * t2.y + x1.y * t2.x) * sc;
            float l6 = (x1.z * t3.x - x1.w * t3.y) * sc;
            float l7 = (x1.z * t3.y + x1.w * t3.x) * sc;
            // physical order: {l0,l4,l1,l5, l2,l6,l3,l7}
            pr[8 * g + 0] = f2tf(l0); pr[8 * g + 1] = f2tf(l4);
            pr[8 * g + 2] = f2tf(l1); pr[8 * g + 3] = f2tf(l5);
            pr[8 * g + 4] = f2tf(l2); pr[8 * g + 5] = f2tf(l6);
            pr[8 * g + 6] = f2tf(l3); pr[8 * g + 7] = f2tf(l7);
        }
    }
    __syncthreads();

    // -------- Q fragments --------
    unsigned qa[2][8][4];
#pragma unroll
    for (int tt = 0; tt < 2; tt++) {
        int r0 = tt * 64 + 16 * w + la;
#pragma unroll
        for (int kk = 0; kk < 8; kk++) {
            uint2 p0 = *reinterpret_cast<const uint2*>(&Ps[r0 * SK + kk * 8 + 2 * lb]);
            uint2 p1 = *reinterpret_cast<const uint2*>(&Ps[(r0 + 8) * SK + kk * 8 + 2 * lb]);
            qa[tt][kk][0] = p0.x; qa[tt][kk][1] = p1.x; qa[tt][kk][2] = p0.y; qa[tt][kk][3] = p1.y;
        }
    }
    __syncthreads();

    float oacc[2][8][4] = {};
    float rm[2][2] = {{-1e30f, -1e30f}, {-1e30f, -1e30f}};
    float ls[2][2] = {};
    const int P0 = pc8(2 * lb), P1 = pc8(2 * lb + 1);
    const int pkey = 16 * w + la;       // warp-strip base row (within a tile)

    for (int i = 0; i < 128; i++) {
        int s = i & 1;
        CP_WAIT1();
        __syncthreads();

        // ---- convert: K rope+permute in place; V transpose+permute into Vt ----
        {
            int t = (kvh * 128 + i) >> 2;
            int krow = tid >> 1, half = tid & 1;
            float* kb = Kr + s * 64 * SK + krow * SK;
            const float2* tt_ = Tab + t * 32 + half * 16;
#pragma unroll
            for (int g2 = 0; g2 < 4; g2++) {
                int ch0 = (half * 4 + g2) * 8;
                float4 a = *reinterpret_cast<const float4*>(kb + ch0);
                float4 b = *reinterpret_cast<const float4*>(kb + ch0 + 4);
                float2 t0 = tt_[4 * g2], t1 = tt_[4 * g2 + 1], t2 = tt_[4 * g2 + 2], t3 = tt_[4 * g2 + 3];
                float l0 = a.x * t0.x - a.y * t0.y;
                float l1 = a.x * t0.y + a.y * t0.x;
                float l2 = a.z * t1.x - a.w * t1.y;
                float l3 = a.z * t1.y + a.w * t1.x;
                float l4 = b.x * t2.x - b.y * t2.y;
                float l5 = b.x * t2.y + b.y * t2.x;
                float l6 = b.z * t3.x - b.w * t3.y;
                float l7 = b.z * t3.y + b.w * t3.x;
                unsigned* o = reinterpret_cast<unsigned*>(kb + ch0);
                o[0] = f2tf(l0); o[1] = f2tf(l4); o[2] = f2tf(l1); o[3] = f2tf(l5);
                o[4] = f2tf(l2); o[5] = f2tf(l6); o[6] = f2tf(l3); o[7] = f2tf(l7);
            }
            float* vb = Vr + s * 64 * SK + krow * SK;
            int pk = (krow & ~7) | pc8(krow & 7);
            unsigned* vt = reinterpret_cast<unsigned*>(Vt);
#pragma unroll
            for (int c = 0; c < 8; c++) {
                int ch0 = half * 32 + c * 4;
                float4 v = *reinterpret_cast<const float4*>(vb + ch0);
                vt[(ch0 + 0) * SK + pk] = f2tf(v.x);
                vt[(ch0 + 1) * SK + pk] = f2tf(v.y);
                vt[(ch0 + 2) * SK + pk] = f2tf(v.z);
                vt[(ch0 + 3) * SK + pk] = f2tf(v.w);
            }
        }
        __syncthreads();

        // ---- per q-tile: S = QK^T, online softmax, P store ----
        const float* Kb = Kr + s * 64 * SK;
#pragma unroll
        for (int tt = 0; tt < 2; tt++) {
            float sc[8][4];
#pragma unroll
            for (int nn = 0; nn < 8; nn++) {
                sc[nn][0] = sc[nn][1] = sc[nn][2] = sc[nn][3] = 0.f;
                const float* kr = Kb + (nn * 8 + la) * SK;
#pragma unroll
                for (int kk = 0; kk < 8; kk++) {
                    uint2 b = *reinterpret_cast<const uint2*>(kr + kk * 8 + 2 * lb);
                    mma8(sc[nn], qa[tt][kk], b.x, b.y);
                }
            }
            float mx0 = -1e30f, mx1 = -1e30f;
#pragma unroll
            for (int nn = 0; nn < 8; nn++) {
                mx0 = fmaxf(mx0, fmaxf(sc[nn][0], sc[nn][1]));
                mx1 = fmaxf(mx1, fmaxf(sc[nn][2], sc[nn][3]));
            }
            mx0 = fmaxf(mx0, __shfl_xor_sync(0xffffffffu, mx0, 1));
            mx0 = fmaxf(mx0, __shfl_xor_sync(0xffffffffu, mx0, 2));
            mx1 = fmaxf(mx1, __shfl_xor_sync(0xffffffffu, mx1, 1));
            mx1 = fmaxf(mx1, __shfl_xor_sync(0xffffffffu, mx1, 2));
            float mn0 = fmaxf(rm[tt][0], mx0), mn1 = fmaxf(rm[tt][1], mx1);
            float al0 = ex2(rm[tt][0] - mn0), al1 = ex2(rm[tt][1] - mn1);
            float s0 = 0.f, s1 = 0.f;
            float* pr0 = Ps + (tt * 64 + pkey) * SK;
            float* pr1 = Ps + (tt * 64 + pkey + 8) * SK;
#pragma unroll
            for (int nn = 0; nn < 8; nn++) {
                float p0 = ex2(sc[nn][0] - mn0);
                float p1 = ex2(sc[nn][1] - mn0);
                float p2 = ex2(sc[nn][2] - mn1);
                float p3 = ex2(sc[nn][3] - mn1);
                s0 += p0 + p1; s1 += p2 + p3;
                pr0[nn * 8 + P0] = p0;  // raw f32 bits as tf32 (HW truncates)
                pr0[nn * 8 + P1] = p1;
                pr1[nn * 8 + P0] = p2;
                pr1[nn * 8 + P1] = p3;
            }
            s0 += __shfl_xor_sync(0xffffffffu, s0, 1);
            s0 += __shfl_xor_sync(0xffffffffu, s0, 2);
            s1 += __shfl_xor_sync(0xffffffffu, s1, 1);
            s1 += __shfl_xor_sync(0xffffffffu, s1, 2);
            ls[tt][0] = ls[tt][0] * al0 + s0;
            ls[tt][1] = ls[tt][1] * al1 + s1;
            rm[tt][0] = mn0; rm[tt][1] = mn1;
#pragma unroll
            for (int nn = 0; nn < 8; nn++) {
                oacc[tt][nn][0] *= al0; oacc[tt][nn][1] *= al0;
                oacc[tt][nn][2] *= al1; oacc[tt][nn][3] *= al1;
            }
        }
        __syncwarp();  // P rows are warp-private

        // ---- O += P V (B-frags shared across both q-tiles) ----
#pragma unroll
        for (int kk = 0; kk < 8; kk++) {
            uint2 a0l = *reinterpret_cast<const uint2*>(&Ps[pkey * SK + kk * 8 + 2 * lb]);
            uint2 a0h = *reinterpret_cast<const uint2*>(&Ps[(pkey + 8) * SK + kk * 8 + 2 * lb]);
            uint2 a1l = *reinterpret_cast<const uint2*>(&Ps[(64 + pkey) * SK + kk * 8 + 2 * lb]);
            uint2 a1h = *reinterpret_cast<const uint2*>(&Ps[(64 + pkey + 8) * SK + kk * 8 + 2 * lb]);
            unsigned A0[4] = {a0l.x, a0h.x, a0l.y, a0h.y};
            unsigned A1[4] = {a1l.x, a1h.x, a1l.y, a1h.y};
#pragma unroll
            for (int nn = 0; nn < 8; nn++) {
                uint2 b = *reinterpret_cast<const uint2*>(&Vt[(nn * 8 + la) * SK + kk * 8 + 2 * lb]);
                mma8(oacc[0][nn], A0, b.x, b.y);
                mma8(oacc[1][nn], A1, b.x, b.y);
            }
        }

        __syncthreads();
        if (i + 2 < 128) issue_tile(i + 2);
        CP_COMMIT();
    }

    // -------- epilogue: write split-KV partials (unnormalized O, m, l) --------
    int pbase = ((bhi * 2 + qp) * 2 + kvh);
    float* po = g_po + (size_t)pbase * 8192;
#pragma unroll
    for (int tt = 0; tt < 2; tt++) {
        int row = tt * 64 + pkey;
#pragma unroll
        for (int nn = 0; nn < 8; nn++) {
            int ch = nn * 8 + 2 * lb;
            po[(ch + 0) * 128 + row]     = oacc[tt][nn][0];
            po[(ch + 1) * 128 + row]     = oacc[tt][nn][1];
            po[(ch + 0) * 128 + row + 8] = oacc[tt][nn][2];
            po[(ch + 1) * 128 + row + 8] = oacc[tt][nn][3];
        }
        if (lb == 0) {
            g_pm[pbase * 128 + row]     = rm[tt][0];
            g_pl[pbase * 128 + row]     = ls[tt][0];
            g_pm[pbase * 128 + row + 8] = rm[tt][1];
            g_pl[pbase * 128 + row + 8] = ls[tt][1];
        }
    }
}

// ---------------- K3b: split-KV combine -> g_o [b][ch*NH+h][s] ----------------
__global__ __launch_bounds__(256) void combine_kernel() {
    int qp = blockIdx.x, head = blockIdx.y, bb = blockIdx.z;
    int pb0 = (((bb * NH + head) * 2 + qp) * 2 + 0);
    int pb1 = pb0 + 1;
    int tid = threadIdx.x;
    __shared__ float w0s[128], w1s[128], il[128];
    if (tid < 128) {
        float m0 = g_pm[pb0 * 128 + tid], m1 = g_pm[pb1 * 128 + tid];
        float l0 = g_pl[pb0 * 128 + tid], l1 = g_pl[pb1 * 128 + tid];
        float M = fmaxf(m0, m1);
        float w0 = ex2(m0 - M), w1 = ex2(m1 - M);
        w0s[tid] = w0; w1s[tid] = w1;
        il[tid] = 1.0f / (w0 * l0 + w1 * l1);
    }
    __syncthreads();
    int ch = tid >> 2, sg = tid & 3;
    const float* p0 = g_po + (size_t)pb0 * 8192 + ch * 128;
    const float* p1 = g_po + (size_t)pb1 * 8192 + ch * 128;
    float* dst = g_o + ((size_t)bb * CDIM + (ch * NH + head)) * HW + qp * 128;
#pragma unroll 4
    for (int rr = 0; rr < 32; rr++) {
        int r = sg * 32 + rr;
        dst[r] = (w0s[r] * p0[r] + w1s[r] * p1[r]) * il[r];
    }
}

// ---------------- K4: proj GEMM + mp_sum ----------------
__global__ __launch_bounds__(256) void proj_kernel(const float* __restrict__ x,
                                                   float* __restrict__ out) {
    __shared__ float As[16][68];
    __shared__ float Bs[16][68];
    int bb = blockIdx.z;
    int m0 = blockIdx.y * 64;
    int n0 = blockIdx.x * 64;
    int tid = threadIdx.x;
    int ty = tid >> 4, tx = tid & 15;
    float acc[4][4] = {};

    for (int k0 = 0; k0 < CDIM; k0 += 16) {
        {
            int lin = tid * 4;
            int mi = lin >> 4, ki = lin & 15;
            float4 a = *reinterpret_cast<const float4*>(&g_wproj_n[(size_t)(m0 + mi) * CDIM + k0 + ki]);
            As[ki + 0][mi] = a.x; As[ki + 1][mi] = a.y; As[ki + 2][mi] = a.z; As[ki + 3][mi] = a.w;
        }
        {
            int lin = tid * 4;
            int ki = lin >> 6, ni = lin & 63;
            float4 b = *reinterpret_cast<const float4*>(&g_o[((size_t)bb * CDIM + k0 + ki) * HW + n0 + ni]);
            *reinterpret_cast<float4*>(&Bs[ki][ni]) = b;
        }
        __syncthreads();
#pragma unroll
        for (int kk = 0; kk < 16; kk++) {
            float4 a = *reinterpret_cast<const float4*>(&As[kk][ty * 4]);
            float4 b = *reinterpret_cast<const float4*>(&Bs[kk][tx * 4]);
            float av[4] = {a.x, a.y, a.z, a.w};
            float bv[4] = {b.x, b.y, b.z, b.w};
#pragma unroll
            for (int i = 0; i < 4; i++)
#pragma unroll
                for (int j = 0; j < 4; j++) acc[i][j] += av[i] * bv[j];
        }
        __syncthreads();
    }

    const float norm = 1.3130643286f;  // 1/sqrt(0.7^2+0.3^2)
#pragma unroll
    for (int i = 0; i < 4; i++) {
        int och = m0 + ty * 4 + i;
#pragma unroll
        for (int j = 0; j < 4; j++) {
            int s = n0 + tx * 4 + j;
            size_t idx = ((size_t)bb * CDIM + och) * HW + s;
            out[idx] = (0.7f * x[idx] + 0.3f * acc[i][j]) * norm;
        }
    }
}

extern "C" void kernel_launch(void* const* d_in, const int* in_sizes, int n_in,
                              void* d_out, int out_size) {
    const float* x     = (const float*)d_in[0];
    const float* ck    = (const float*)d_in[1];
    const float* cv    = (const float*)d_in[2];
    const float* wqkv  = (const float*)d_in[3];
    const float* wproj = (const float*)d_in[4];
    float* out = (float*)d_out;

    norm_kernel<<<4 * CDIM, 128>>>(wqkv, wproj);
    rope_table_kernel<<<8, 256>>>();
    qkv_gemm_kernel<<<dim3(4, 24, 4), 256>>>(x);

    int smem = (7 * 64 * SK + 64 * 32 * 2) * (int)sizeof(float);  // 145408 B
    cudaFuncSetAttribute(attn_kernel, cudaFuncAttributeMaxDynamicSharedMemorySize, smem);
    attn_kernel<<<dim3(4, NH, 4), 128, smem>>>(ck, cv);

    combine_kernel<<<dim3(2, NH, BATCH), 256>>>();
    proj_kernel<<<dim3(4, 8, 4), 256>>>(x, out);
}